// round 12
// baseline (speedup 1.0000x reference)
#include <cuda_runtime.h>

#define B_  16
#define N_  4096
#define D_  1024
#define K_  2048

#define TOK_ 64
#define BLKS_PER_B_ (N_ / TOK_)   // 64
#define PF_BLKS_ 256              // prefetch blocks (32 rows each = 32MB total)

__device__ unsigned       g_seg[B_ * N_];          // packed tie-keys by segment
__device__ unsigned short g_pref[B_ * (N_ + 1)];   // exclusive bin prefix + sentinel
__device__ float g_part[B_ * BLKS_PER_B_ * D_];    // pruned partials (4MB)
__device__ int   g_done[B_];                        // fused completion counters
__device__ float g_sink[32768];                     // prefetch sink (never read)

__device__ __forceinline__ unsigned ord32(float v) {
    unsigned bits = __float_as_uint(v);
    return (bits & 0x80000000u) ? ~bits : (bits | 0x80000000u);
}

// -------------------------------------------------------------------------
// K1: blocks [0,16)   -> per-batch bin structure (histogram of top-12-bit
//                        reversed key bins, exclusive scan, scatter of
//                        packed u32 tie-keys (key<<12)|(4095-idx) into gmem
//                        segments) + zero this batch's g_done counter.
//     blocks [16,272) -> prefetch rows [0,512) of each batch into L2 —
//                        exactly what fused's first iterations read.
// -------------------------------------------------------------------------
__global__ void __launch_bounds__(1024)
k1_bins_prefetch(const float* __restrict__ attn, const float* __restrict__ seq) {
    const int t = threadIdx.x;

    if (blockIdx.x < B_) {
        __shared__ unsigned       atom[N_ / 2];   // 8KB packed counters
        __shared__ unsigned short pref[N_];       // 8KB
        __shared__ int warp_tot[32];

        const int b = blockIdx.x;
        if (t == 0) g_done[b] = 0;                // reset for this replay

        unsigned key[4];
        #pragma unroll
        for (int p = 0; p < 4; p++)
            key[p] = ord32(attn[b * N_ + p * 1024 + t]);
        atom[t] = 0u; atom[t + 1024] = 0u;
        __syncthreads();

        #pragma unroll
        for (int p = 0; p < 4; p++) {
            const unsigned bin = 4095u - (key[p] >> 20);
            atomicAdd(&atom[bin >> 1], 1u << ((bin & 1u) * 16));
        }
        __syncthreads();

        // exclusive scan over 4096 bins (thread t owns bins 4t..4t+3)
        const unsigned w0 = atom[2 * t], w1 = atom[2 * t + 1];
        const int c0 = w0 & 0xFFFF, c1 = w0 >> 16;
        const int c2 = w1 & 0xFFFF, c3 = w1 >> 16;
        const int local = c0 + c1 + c2 + c3;
        const int lane = t & 31, wid = t >> 5;

        int scan = local;
        #pragma unroll
        for (int d = 1; d < 32; d <<= 1) {
            const int v = __shfl_up_sync(0xffffffffu, scan, d);
            if (lane >= d) scan += v;
        }
        if (lane == 31) warp_tot[wid] = scan;
        __syncthreads();
        if (wid == 0) {
            const int v = warp_tot[lane];
            int s = v;
            #pragma unroll
            for (int d = 1; d < 32; d <<= 1) {
                const int u = __shfl_up_sync(0xffffffffu, s, d);
                if (lane >= d) s += u;
            }
            warp_tot[lane] = s - v;
        }
        __syncthreads();
        const int off = warp_tot[wid] + (scan - local);
        const unsigned short p0 = (unsigned short)(off);
        const unsigned short p1 = (unsigned short)(off + c0);
        const unsigned short p2 = (unsigned short)(off + c0 + c1);
        const unsigned short p3 = (unsigned short)(off + c0 + c1 + c2);
        pref[4 * t] = p0; pref[4 * t + 1] = p1;
        pref[4 * t + 2] = p2; pref[4 * t + 3] = p3;
        unsigned short* __restrict__ gp = g_pref + b * (N_ + 1);
        gp[4 * t] = p0; gp[4 * t + 1] = p1;
        gp[4 * t + 2] = p2; gp[4 * t + 3] = p3;
        if (t == 0) gp[N_] = (unsigned short)N_;   // sentinel
        atom[2 * t] = 0u; atom[2 * t + 1] = 0u;
        __syncthreads();

        #pragma unroll
        for (int p = 0; p < 4; p++) {
            const int i = p * 1024 + t;
            const unsigned bin = 4095u - (key[p] >> 20);
            const unsigned sh  = (bin & 1u) * 16;
            const unsigned old = atomicAdd(&atom[bin >> 1], 1u << sh);
            const int pos = (int)pref[bin] + (int)((old >> sh) & 0xFFFFu);
            g_seg[b * N_ + pos] = (key[p] << 12) | (unsigned)(4095 - i);
        }
    } else {
        // ---------- prefetch rows [0,512) per batch into L2 ----------
        const int s  = blockIdx.x - B_;      // 0..255
        const int b  = s >> 4;
        const int c  = s & 15;
        const int g  = t >> 8;               // 0..3
        const int tt = t & 255;
        const int n0 = c * 32 + g * 8;       // 32 rows/block, 8/group

        const float4* __restrict__ src =
            reinterpret_cast<const float4*>(seq + ((size_t)(b * N_ + n0)) * D_);

        float4 a = make_float4(0.f, 0.f, 0.f, 0.f);
        #pragma unroll
        for (int r = 0; r < 8; r++) {
            const float4 v = src[(size_t)r * (D_ / 4) + tt];
            a.x += v.x; a.y += v.y; a.z += v.z; a.w += v.w;
        }
        reinterpret_cast<float4*>(g_sink)[(((s * 4 + g) & 31) * 256) + tt] = a;
    }
}

// -------------------------------------------------------------------------
// K2: fused rank-count + gather + pruned-sum + folded rem.
// grid (BLKS_PER_B, B) = 1024 blocks (all co-resident), block 256.
// Threads 0..63 first compute the block's 64 ranks from the L2-resident
// bin structure (rank = pref[bin] + #(seg[q] > packed_key); order-invariant,
// exactly jax.lax.top_k's value-desc/index-asc order). The block then
// streams 64 rows (256KB sequential, __ldcs): selected rows -> out[b,rank,:]
// via __stcs; pruned rows -> per-block partial. The last block to finish a
// batch (atomic counter, zeroed by K1) reduces that batch's 64 partials in
// fixed order and writes the mixup row (2048 + 1e-10 == 2048.0f in fp32).
// -------------------------------------------------------------------------
__global__ void __launch_bounds__(256)
fused_kernel(const float* __restrict__ seq, const float* __restrict__ attn,
             float* __restrict__ out) {
    __shared__ int srank[TOK_];
    __shared__ int sdone;
    const int b   = blockIdx.y;
    const int blk = blockIdx.x;
    const int t   = threadIdx.x;
    const int n0  = blk * TOK_;

    if (t < TOK_) {
        const int i = n0 + t;
        const unsigned key = ord32(attn[b * N_ + i]);
        const unsigned ki  = (key << 12) | (unsigned)(4095 - i);
        const unsigned bin = 4095u - (key >> 20);
        const unsigned short* __restrict__ gp = g_pref + b * (N_ + 1);
        const int s0  = gp[bin];
        const int end = gp[bin + 1];
        const unsigned* __restrict__ sg = g_seg + b * N_;
        int r = s0;
        for (int q = s0; q < end; q++) r += (sg[q] > ki);
        srank[t] = r;
    }
    __syncthreads();

    const float4* __restrict__ src =
        reinterpret_cast<const float4*>(seq + ((size_t)(b * N_ + n0)) * D_);

    float4 acc = make_float4(0.f, 0.f, 0.f, 0.f);

    #pragma unroll 8
    for (int k = 0; k < TOK_; k++) {
        const float4 v = __ldcs(src + (size_t)k * (D_ / 4) + t);
        const int r = srank[k];
        if (r < K_) {
            __stcs(reinterpret_cast<float4*>(
                       out + ((size_t)(b * (K_ + 1) + r)) * D_) + t, v);
        } else {
            acc.x += v.x; acc.y += v.y; acc.z += v.z; acc.w += v.w;
        }
    }

    float4* __restrict__ gp4 = reinterpret_cast<float4*>(g_part);
    gp4[((size_t)b * BLKS_PER_B_ + blk) * (D_ / 4) + t] = acc;

    __threadfence();
    if (t == 0) sdone = atomicAdd(&g_done[b], 1) + 1;
    __syncthreads();

    if (sdone == BLKS_PER_B_) {
        // last block for this batch: reduce 64 partials (fixed order) -> rem row
        const float4* __restrict__ p =
            reinterpret_cast<const float4*>(g_part) +
            (size_t)b * BLKS_PER_B_ * (D_ / 4) + t;
        float4 s = make_float4(0.f, 0.f, 0.f, 0.f);
        #pragma unroll 8
        for (int j = 0; j < BLKS_PER_B_; j++) {
            const float4 v = p[(size_t)j * (D_ / 4)];
            s.x += v.x; s.y += v.y; s.z += v.z; s.w += v.w;
        }
        const float sc = 0.05f / 2048.0f;
        s.x *= sc; s.y *= sc; s.z *= sc; s.w *= sc;
        reinterpret_cast<float4*>(
            out + ((size_t)(b * (K_ + 1) + K_)) * D_)[t] = s;
    }
}

extern "C" void kernel_launch(void* const* d_in, const int* in_sizes, int n_in,
                              void* d_out, int out_size) {
    const float* seq  = (const float*)d_in[0];   // (16, 4096, 1024) fp32
    const float* attn = (const float*)d_in[1];   // (16, 4096) fp32
    float* out = (float*)d_out;                  // (16, 2049, 1024) fp32
    (void)in_sizes; (void)n_in; (void)out_size;

    k1_bins_prefetch<<<B_ + PF_BLKS_, 1024>>>(attn, seq);
    fused_kernel    <<<dim3(BLKS_PER_B_, B_), 256>>>(seq, attn, out);
}

// round 13
// speedup vs baseline: 1.2674x; 1.2674x over previous
#include <cuda_runtime.h>

#define B_  16
#define N_  4096
#define D_  1024
#define K_  2048

#define TOK_ 32
#define BLKS_PER_B_ (N_ / TOK_)   // 128
#define PF_BLKS_ 256              // prefetch blocks (32 rows each = 32MB total)

__device__ unsigned       g_seg[B_ * N_];          // packed tie-keys by segment
__device__ unsigned short g_pref[B_ * (N_ + 1)];   // exclusive bin prefix + sentinel
__device__ float g_part[B_ * BLKS_PER_B_ * D_];    // pruned partials (8MB)
__device__ float g_sink[32768];                    // prefetch sink (never read)

__device__ __forceinline__ unsigned ord32(float v) {
    unsigned bits = __float_as_uint(v);
    return (bits & 0x80000000u) ? ~bits : (bits | 0x80000000u);
}

// -------------------------------------------------------------------------
// K1: blocks [0,16)   -> per-batch bin structure: histogram of top-12-bit
//                        (reversed) key bins, exclusive scan, scatter of
//                        packed u32 tie-keys (key<<12)|(4095-idx) into gmem
//                        segments.
//     blocks [16,272) -> prefetch rows [0,512) of each batch into L2 —
//                        exactly what fused's first iterations read.
// -------------------------------------------------------------------------
__global__ void __launch_bounds__(1024)
k1_bins_prefetch(const float* __restrict__ attn, const float* __restrict__ seq) {
    const int t = threadIdx.x;

    if (blockIdx.x < B_) {
        __shared__ unsigned       atom[N_ / 2];   // 8KB packed counters
        __shared__ unsigned short pref[N_];       // 8KB
        __shared__ int warp_tot[32];

        const int b = blockIdx.x;

        unsigned key[4];
        #pragma unroll
        for (int p = 0; p < 4; p++)
            key[p] = ord32(attn[b * N_ + p * 1024 + t]);
        atom[t] = 0u; atom[t + 1024] = 0u;
        __syncthreads();

        #pragma unroll
        for (int p = 0; p < 4; p++) {
            const unsigned bin = 4095u - (key[p] >> 20);
            atomicAdd(&atom[bin >> 1], 1u << ((bin & 1u) * 16));
        }
        __syncthreads();

        // exclusive scan over 4096 bins (thread t owns bins 4t..4t+3)
        const unsigned w0 = atom[2 * t], w1 = atom[2 * t + 1];
        const int c0 = w0 & 0xFFFF, c1 = w0 >> 16;
        const int c2 = w1 & 0xFFFF, c3 = w1 >> 16;
        const int local = c0 + c1 + c2 + c3;
        const int lane = t & 31, wid = t >> 5;

        int scan = local;
        #pragma unroll
        for (int d = 1; d < 32; d <<= 1) {
            const int v = __shfl_up_sync(0xffffffffu, scan, d);
            if (lane >= d) scan += v;
        }
        if (lane == 31) warp_tot[wid] = scan;
        __syncthreads();
        if (wid == 0) {
            const int v = warp_tot[lane];
            int s = v;
            #pragma unroll
            for (int d = 1; d < 32; d <<= 1) {
                const int u = __shfl_up_sync(0xffffffffu, s, d);
                if (lane >= d) s += u;
            }
            warp_tot[lane] = s - v;
        }
        __syncthreads();
        const int off = warp_tot[wid] + (scan - local);
        const unsigned short p0 = (unsigned short)(off);
        const unsigned short p1 = (unsigned short)(off + c0);
        const unsigned short p2 = (unsigned short)(off + c0 + c1);
        const unsigned short p3 = (unsigned short)(off + c0 + c1 + c2);
        pref[4 * t] = p0; pref[4 * t + 1] = p1;
        pref[4 * t + 2] = p2; pref[4 * t + 3] = p3;
        unsigned short* __restrict__ gp = g_pref + b * (N_ + 1);
        gp[4 * t] = p0; gp[4 * t + 1] = p1;
        gp[4 * t + 2] = p2; gp[4 * t + 3] = p3;
        if (t == 0) gp[N_] = (unsigned short)N_;   // sentinel
        atom[2 * t] = 0u; atom[2 * t + 1] = 0u;
        __syncthreads();

        #pragma unroll
        for (int p = 0; p < 4; p++) {
            const int i = p * 1024 + t;
            const unsigned bin = 4095u - (key[p] >> 20);
            const unsigned sh  = (bin & 1u) * 16;
            const unsigned old = atomicAdd(&atom[bin >> 1], 1u << sh);
            const int pos = (int)pref[bin] + (int)((old >> sh) & 0xFFFFu);
            g_seg[b * N_ + pos] = (key[p] << 12) | (unsigned)(4095 - i);
        }
    } else {
        // ---------- prefetch rows [0,512) per batch into L2 ----------
        const int s  = blockIdx.x - B_;      // 0..255
        const int b  = s >> 4;
        const int c  = s & 15;
        const int g  = t >> 8;               // 0..3
        const int tt = t & 255;
        const int n0 = c * 32 + g * 8;       // 32 rows/block, 8/group

        const float4* __restrict__ src =
            reinterpret_cast<const float4*>(seq + ((size_t)(b * N_ + n0)) * D_);

        float4 a = make_float4(0.f, 0.f, 0.f, 0.f);
        #pragma unroll
        for (int r = 0; r < 8; r++) {
            const float4 v = src[(size_t)r * (D_ / 4) + tt];
            a.x += v.x; a.y += v.y; a.z += v.z; a.w += v.w;
        }
        reinterpret_cast<float4*>(g_sink)[(((s * 4 + g) & 31) * 256) + tt] = a;
    }
}

// -------------------------------------------------------------------------
// K2: fused rank-count + gather + pruned-sum (R11-proven form).
// grid (BLKS_PER_B, B), block 256. Threads 0..31 compute the block's 32
// ranks from the L2-resident bin structure (rank = pref[bin] +
// #(seg[q] > packed_key); order-invariant, exactly jax.lax.top_k's
// value-desc/index-asc order). Then the block streams 32 rows (128KB
// sequential): selected -> out[b, rank, :], pruned -> per-block partial.
// -------------------------------------------------------------------------
__global__ void __launch_bounds__(256)
fused_kernel(const float* __restrict__ seq, const float* __restrict__ attn,
             float* __restrict__ out) {
    __shared__ int srank[TOK_];
    const int b   = blockIdx.y;
    const int blk = blockIdx.x;
    const int t   = threadIdx.x;
    const int n0  = blk * TOK_;

    if (t < TOK_) {
        const int i = n0 + t;
        const unsigned key = ord32(attn[b * N_ + i]);
        const unsigned ki  = (key << 12) | (unsigned)(4095 - i);
        const unsigned bin = 4095u - (key >> 20);
        const unsigned short* __restrict__ gp = g_pref + b * (N_ + 1);
        const int s0  = gp[bin];
        const int end = gp[bin + 1];
        const unsigned* __restrict__ sg = g_seg + b * N_;
        int r = s0;
        for (int q = s0; q < end; q++) r += (sg[q] > ki);
        srank[t] = r;
    }
    __syncthreads();

    const float4* __restrict__ src =
        reinterpret_cast<const float4*>(seq + ((size_t)(b * N_ + n0)) * D_);

    float4 acc = make_float4(0.f, 0.f, 0.f, 0.f);

    #pragma unroll 8
    for (int k = 0; k < TOK_; k++) {
        const float4 v = src[k * (D_ / 4) + t];
        const int r = srank[k];
        if (r < K_) {
            reinterpret_cast<float4*>(
                out + ((size_t)(b * (K_ + 1) + r)) * D_)[t] = v;
        } else {
            acc.x += v.x; acc.y += v.y; acc.z += v.z; acc.w += v.w;
        }
    }

    reinterpret_cast<float4*>(g_part)
        [((size_t)b * BLKS_PER_B_ + blk) * (D_ / 4) + t] = acc;
}

// -------------------------------------------------------------------------
// K3: reduce pruned partials, write mixup row out[b, K, :].
// grid (B, 16), block 256. rem_cnt = 2048 + 1e-10 == 2048.0f in fp32.
// -------------------------------------------------------------------------
__global__ void __launch_bounds__(256)
rem_kernel(float* __restrict__ out) {
    const int b  = blockIdx.x;
    const int g  = threadIdx.x & 15;
    const int s  = threadIdx.x >> 4;
    const int c4 = blockIdx.y * 16 + g;

    const float4* __restrict__ p =
        reinterpret_cast<const float4*>(g_part) +
        (size_t)b * BLKS_PER_B_ * (D_ / 4) + c4;

    float4 a = make_float4(0.f, 0.f, 0.f, 0.f);
    #pragma unroll
    for (int m = 0; m < 8; m++) {
        const float4 v = p[(size_t)(s + 16 * m) * (D_ / 4)];
        a.x += v.x; a.y += v.y; a.z += v.z; a.w += v.w;
    }

    __shared__ float4 red[16][16];
    red[s][g] = a;
    __syncthreads();

    #pragma unroll
    for (int step = 8; step >= 1; step >>= 1) {
        if (s < step) {
            float4 o = red[s + step][g];
            red[s][g].x += o.x; red[s][g].y += o.y;
            red[s][g].z += o.z; red[s][g].w += o.w;
        }
        __syncthreads();
    }

    if (s == 0) {
        const float sc = 0.05f / 2048.0f;
        float4 r = red[0][g];
        r.x *= sc; r.y *= sc; r.z *= sc; r.w *= sc;
        reinterpret_cast<float4*>(
            out + ((size_t)(b * (K_ + 1) + K_)) * D_)[c4] = r;
    }
}

extern "C" void kernel_launch(void* const* d_in, const int* in_sizes, int n_in,
                              void* d_out, int out_size) {
    const float* seq  = (const float*)d_in[0];   // (16, 4096, 1024) fp32
    const float* attn = (const float*)d_in[1];   // (16, 4096) fp32
    float* out = (float*)d_out;                  // (16, 2049, 1024) fp32
    (void)in_sizes; (void)n_in; (void)out_size;

    k1_bins_prefetch<<<B_ + PF_BLKS_, 1024>>>(attn, seq);
    fused_kernel    <<<dim3(BLKS_PER_B_, B_), 256>>>(seq, attn, out);
    rem_kernel      <<<dim3(B_, 16), 256>>>(out);
}